// round 17
// baseline (speedup 1.0000x reference)
#include <cuda_runtime.h>
#include <cuda_bf16.h>
#include <math.h>

// ARIMA loss with the 32-tap FIR on tensor cores via baseline mma.sync (HMMA):
//   D[m][n] = sum_k A[m,k]*Bcol[n,k];  A[m][k]=y[tb+32m+1+k] (bf16),
//   Bcol[n][k]=g[k-n] (Toeplitz)  =>  D[m][n] = FIR(t=tb+32m+n), fp32 accum.
// Per CTA: 128x32x64 GEMM = 8 warps x 16 mma.sync.m16n8k16. Scalar pipes keep
// only staging + sliding mean/var + epilogue (16 t per thread).

#define PW    32
#define T0C   33
#define EPSF  1e-5f
#define TPB   256
#define CTAT  4096               // 128 m-rows x 32 n-cols of t per CTA
#define NCH   1033               // 16B chunks staged: floats [0, 4132)
#define SYF   4160
#define MAXB  512

#define SWZ(b) ((b) ^ (((b) >> 3) & 0x70))

__device__ float    g_part[MAXB];
__device__ unsigned g_ctr = 0;

__device__ __forceinline__ float sqrt_apx(float x) {
    float r; asm("sqrt.approx.f32 %0, %1;" : "=f"(r) : "f"(x)); return r;
}
__device__ __forceinline__ unsigned bfpair(float lo, float hi) {   // bits[15:0]=lo
    unsigned r;
    asm("cvt.rn.satfinite.bf16x2.f32 %0, %1, %2;" : "=r"(r) : "f"(hi), "f"(lo));
    return r;
}
__device__ __forceinline__ void mma16816(
    float& d0, float& d1, float& d2, float& d3,
    unsigned a0, unsigned a1, unsigned a2, unsigned a3,
    unsigned b0, unsigned b1)
{
    asm volatile(
        "mma.sync.aligned.m16n8k16.row.col.f32.bf16.bf16.f32 "
        "{%0,%1,%2,%3}, {%4,%5,%6,%7}, {%8,%9}, {%0,%1,%2,%3};"
        : "+f"(d0), "+f"(d1), "+f"(d2), "+f"(d3)
        : "r"(a0), "r"(a1), "r"(a2), "r"(a3), "r"(b0), "r"(b1));
}

struct Smem {
    __align__(1024) unsigned char AD[128 * 128];  // A bf16 [128][64] -> reused as D f32 [128][32]
    __align__(1024) unsigned char Bt[32 * 128];   // Bcol bf16 [32][64] (n-major), SW128
    __align__(16)   float sy[SYF];                // swizzled fp32 stage of y[tb ..]
    float  sg[PW];
    float  sc[3];
    double sred[8];
    int    isLast;
};

__global__ void __launch_bounds__(TPB, 2) arima_mma(
    const float* __restrict__ y, const float* __restrict__ w,
    const float* __restrict__ ab, const float* __restrict__ rw_,
    const float* __restrict__ rb_, float* __restrict__ out, int T, int S)
{
    __shared__ Smem sm;
    const int tid = threadIdx.x;
    const int bid = blockIdx.x;
    const int tb  = bid * CTAT;
    const int wid = tid >> 5;
    const int lid = tid & 31;

    // Phase 1: taps + constants
    if (tid < PW) {
        float wj  = w[tid];
        float wj1 = (tid < PW - 1) ? w[tid + 1] : 0.0f;
        float gv  = wj - wj1;
        if (tid == PW - 2) gv -= 1.0f;
        if (tid == PW - 1) gv += 1.0f;
        sm.sg[tid] = gv;
    }
    if (tid == 0) {
        float rw = rw_[0], rb = rb_[0], b = ab[0], w0 = w[0];
        float denom = rw + EPSF * EPSF;
        float K1 = rw / denom;
        sm.sc[0] = K1;
        sm.sc[1] = ((w0 * rb - rb + b) / denom) * (1.0f / 32.0f);   // K2q
        sm.sc[2] = fmaf(K1, w0, -1.0f) * (1.0f / 32.0f);            // M1q
    }

    // Phase 2: coalesced fp32 stage (swizzled), zero-padded past S
    {
        const float4* y4 = (const float4*)(y + tb);
        #pragma unroll
        for (int c = 0; c < 5; c++) {
            int i = tid + c * TPB;
            if (i < NCH) {
                int gf = tb + 4 * i;
                float4 v;
                if (gf + 3 < S) v = y4[i];
                else {
                    v.x = (gf     < S) ? y[gf]     : 0.f;
                    v.y = (gf + 1 < S) ? y[gf + 1] : 0.f;
                    v.z = (gf + 2 < S) ? y[gf + 2] : 0.f;
                    v.w = (gf + 3 < S) ? y[gf + 3] : 0.f;
                }
                *(float4*)((char*)sm.sy + SWZ(16 * i)) = v;
            }
        }
    }
    __syncthreads();

    // Phase 3: build Bcol[n][k]=g[k-n] (bf16, SW128) and A[m][k]=y[32m+1+k] (bf16, SW128)
    #pragma unroll
    for (int q = 0; q < 8; q++) {                    // 32x64 B entries
        int idx = tid + q * TPB;
        int n = idx >> 6, k = idx & 63, j = k - n;
        float gv = (j >= 0 && j < PW) ? sm.sg[j] : 0.0f;
        *(__nv_bfloat16*)((char*)sm.Bt + SWZ((unsigned)(n * 128 + 2 * k))) =
            __float2bfloat16(gv);
    }
    {
        const int m = tid >> 1, kb = (tid & 1) * 32;
        #pragma unroll
        for (int j = 0; j < 16; j++) {
            int k  = kb + 2 * j;
            int yi = 32 * m + 1 + k;
            float f0 = *(const float*)((const char*)sm.sy + SWZ(4 * yi));
            float f1 = *(const float*)((const char*)sm.sy + SWZ(4 * (yi + 1)));
            *(unsigned*)((char*)sm.AD + SWZ((unsigned)(m * 128 + 2 * k))) = bfpair(f0, f1);
        }
    }
    __syncthreads();

    // Phase 4: MMA — warp wid owns rows [16*wid, 16*wid+16), all 32 cols
    const int gid = lid >> 2, tig = lid & 3;
    const int r1 = 16 * wid + gid, r2 = r1 + 8;
    unsigned af[4][4];
    #pragma unroll
    for (int kk = 0; kk < 4; kk++) {
        int c = 2 * tig + 16 * kk;
        af[kk][0] = *(const unsigned*)((const char*)sm.AD + SWZ((unsigned)(r1 * 128 + 2 * c)));
        af[kk][1] = *(const unsigned*)((const char*)sm.AD + SWZ((unsigned)(r2 * 128 + 2 * c)));
        af[kk][2] = *(const unsigned*)((const char*)sm.AD + SWZ((unsigned)(r1 * 128 + 2 * (c + 8))));
        af[kk][3] = *(const unsigned*)((const char*)sm.AD + SWZ((unsigned)(r2 * 128 + 2 * (c + 8))));
    }
    float dd[4][4];
    #pragma unroll
    for (int nt = 0; nt < 4; nt++) {
        int n = gid + 8 * nt;
        float d0 = 0.f, d1 = 0.f, d2 = 0.f, d3 = 0.f;
        #pragma unroll
        for (int kk = 0; kk < 4; kk++) {
            int k0 = 2 * tig + 16 * kk;
            unsigned b0 = *(const unsigned*)((const char*)sm.Bt + SWZ((unsigned)(n * 128 + 2 * k0)));
            unsigned b1 = *(const unsigned*)((const char*)sm.Bt + SWZ((unsigned)(n * 128 + 2 * (k0 + 8))));
            mma16816(d0, d1, d2, d3, af[kk][0], af[kk][1], af[kk][2], af[kk][3], b0, b1);
        }
        dd[nt][0] = d0; dd[nt][1] = d1; dd[nt][2] = d2; dd[nt][3] = d3;
    }
    __syncthreads();                                 // all warps done reading A

    // Phase 5: store D over the A region: D f32 [128 rows][32 cols], 128B rows, SWZ
    #pragma unroll
    for (int nt = 0; nt < 4; nt++) {
        unsigned co = (unsigned)(8 * tig + 32 * nt);
        *(float2*)((char*)sm.AD + SWZ((unsigned)(r1 * 128) + co)) = make_float2(dd[nt][0], dd[nt][1]);
        *(float2*)((char*)sm.AD + SWZ((unsigned)(r2 * 128) + co)) = make_float2(dd[nt][2], dd[nt][3]);
    }
    __syncthreads();

    // Phase 6: scalar epilogue — thread covers t0..t0+15, FIR from D
    const float K1 = sm.sc[0], K2q = sm.sc[1], M1q = sm.sc[2];
    const float C0 = 1024.0f * EPSF;
    const int m    = tid & 127;
    const int half = tid >> 7;
    const int t0   = tb + 32 * m + 16 * half;

    float xa[52];
    {
        const int cbase = 8 * m + 4 * half;
        #pragma unroll
        for (int c = 0; c < 13; c++) {
            float4 v = *(const float4*)((const char*)sm.sy + SWZ(16 * (cbase + c)));
            xa[4*c+0] = v.x; xa[4*c+1] = v.y; xa[4*c+2] = v.z; xa[4*c+3] = v.w;
        }
    }
    float fir[16];
    #pragma unroll
    for (int c = 0; c < 4; c++) {
        float4 v = *(const float4*)((const char*)sm.AD + SWZ((unsigned)(m * 128 + 64 * half + 16 * c)));
        fir[4*c+0] = v.x; fir[4*c+1] = v.y; fir[4*c+2] = v.z; fir[4*c+3] = v.w;
    }

    float sum = 0.f, sq = 0.f;
    #pragma unroll
    for (int i = 1; i <= 32; i++) {
        sum += xa[i];
        sq   = fmaf(xa[i], xa[i], sq);
    }
    float esum_f = 0.0f;
    #pragma unroll
    for (int n = 0; n < 16; n++) {
        if (n > 0) {
            float xn = xa[32 + n], xo = xa[n];
            sum += xn - xo;
            sq   = fmaf(xn, xn, sq);
            sq   = fmaf(-xo, xo, sq);
        }
        float u   = fmaf(-sum, sum, fmaf(32.0f, sq, C0));
        float sd  = sqrt_apx(u);
        float err = fmaf(-K2q, sd, fmaf(M1q, sum, fmaf(-K1, fir[n], xa[33 + n])));
        if (t0 + n < T)
            esum_f = fmaf(err, err, esum_f);
    }

    // Block reduction + fused last-block finish
    double esum = (double)esum_f;
    #pragma unroll
    for (int o = 16; o > 0; o >>= 1)
        esum += __shfl_down_sync(0xffffffffu, esum, o);
    if (lid == 0) sm.sred[wid] = esum;
    __syncthreads();
    if (tid == 0) {
        double bs = 0.0;
        #pragma unroll
        for (int i = 0; i < 8; i++) bs += sm.sred[i];
        g_part[bid] = (float)bs;
        __threadfence();
        unsigned pos = atomicInc(&g_ctr, gridDim.x - 1);
        sm.isLast = (pos == gridDim.x - 1);
    }
    __syncthreads();

    if (sm.isLast) {
        __threadfence();
        double s = 0.0;
        for (int i = tid; i < (int)gridDim.x; i += TPB) s += (double)g_part[i];
        for (int i = tid; i < T0C; i += TPB) { double v = (double)y[i]; s += v * v; }
        #pragma unroll
        for (int o = 16; o > 0; o >>= 1)
            s += __shfl_down_sync(0xffffffffu, s, o);
        if (lid == 0) sm.sred[wid] = s;
        __syncthreads();
        if (tid == 0) {
            double tot = 0.0;
            #pragma unroll
            for (int i = 0; i < 8; i++) tot += sm.sred[i];
            out[0] = (float)(tot / (double)S);
        }
    }
}

extern "C" void kernel_launch(void* const* d_in, const int* in_sizes, int n_in,
                              void* d_out, int out_size)
{
    const float* y  = (const float*)d_in[0];
    const float* w  = (const float*)d_in[1];
    const float* ab = (const float*)d_in[2];
    const float* rw = (const float*)d_in[3];
    const float* rb = (const float*)d_in[4];
    int S = in_sizes[0];
    int T = S - T0C;
    int nblocks = (T + CTAT - 1) / CTAT;   // S=1M -> 256 CTAs
    if (nblocks > MAXB) nblocks = MAXB;
    arima_mma<<<nblocks, TPB>>>(y, w, ab, rw, rb, (float*)d_out, T, S);
}